// round 16
// baseline (speedup 1.0000x reference)
#include <cuda_runtime.h>
#include <cuda_fp16.h>

// Fixed problem shapes
#define NN 20000      // nodes
#define EE 640000     // edges
#define HH 128        // hidden
#define FF 64         // input features
#define RR 8          // relations
#define BB 4          // blocks
#define CC 32         // block size
#define DD 3          // edge-attr dims (j)
#define JR 24         // DD*RR

// -------- device scratch (allocation-free rule) --------
__device__ float    g_h0[NN * HH];                        // x @ feature_emb
__device__ float    g_h1[3 * NN * HH];                    // layer-0 outputs / layer-1 input
__device__ float    g_agg[DD * NN * HH];                  // per-layer aggregated terms, all 3 j
__device__ __half2  g_sums_h[(size_t)JR * NN * 64];       // mean sums [jr][n][64 half2] (123 MB)
__device__ int      g_deg[NN];
__device__ int      g_start[NN + 1];
__device__ int      g_fill[NN];
__device__ int      g_cnt24[JR * NN];                     // per-(j,r,dst) counts (h-independent)
__device__ unsigned g_einfo[EE];                          // src | r0<<15 | r1<<18 | r2<<21

// ---- packed f32x2 helpers (Blackwell; ptxas won't auto-fuse) ----
static __device__ __forceinline__ unsigned long long pk2(float lo, float hi) {
    unsigned long long r;
    asm("mov.b64 %0, {%1, %2};" : "=l"(r) : "f"(lo), "f"(hi));
    return r;
}
static __device__ __forceinline__ void upk2(unsigned long long v, float& lo, float& hi) {
    asm("mov.b64 {%0, %1}, %2;" : "=f"(lo), "=f"(hi) : "l"(v));
}
#define FMA2(acc, a, b) \
    asm("fma.rn.f32x2 %0, %1, %2, %0;" : "+l"(acc) : "l"(a), "l"(b))

// ============================================================
// h0 = x @ feature_emb   (N x 64) @ (64 x 128); 2 rows/block
// also zeroes g_deg for the CSR build
// ============================================================
__global__ __launch_bounds__(256)
void gemm_in_kernel(const float* __restrict__ x, const float* __restrict__ fe) {
    int gt = blockIdx.x * 256 + threadIdx.x;
    if (gt < NN) g_deg[gt] = 0;

    int n = blockIdx.x * 2 + (threadIdx.x >> 7);
    int o = threadIdx.x & 127;
    const float* xr = x + (size_t)n * FF;
    float acc = 0.f;
#pragma unroll
    for (int f = 0; f < FF; f++)
        acc += xr[f] * fe[f * HH + o];
    g_h0[(size_t)n * HH + o] = acc;
}

// ============================================================
// CSR build; k_count also zeroes g_cnt24 (JR*NN=480000 <= EE threads)
// ============================================================
__global__ __launch_bounds__(256)
void k_count(const int* __restrict__ dst) {
    int e = blockIdx.x * 256 + threadIdx.x;
    if (e < JR * NN) g_cnt24[e] = 0;
    if (e < EE) atomicAdd(&g_deg[dst[e]], 1);
}

// single block, 1024 threads; chunk of 20 per thread (covers 20480 >= NN)
__global__ __launch_bounds__(1024)
void k_prefix() {
    __shared__ int partial[1024];
    int t = threadIdx.x;
    const int CH = 20;
    int base = t * CH;
    int local[CH];
    int s = 0;
#pragma unroll
    for (int k = 0; k < CH; k++) {
        int i = base + k;
        int v = (i < NN) ? g_deg[i] : 0;
        local[k] = s;      // exclusive within chunk
        s += v;
    }
    partial[t] = s;
    __syncthreads();
    for (int off = 1; off < 1024; off <<= 1) {
        int v = (t >= off) ? partial[t - off] : 0;
        __syncthreads();
        partial[t] += v;
        __syncthreads();
    }
    int prev = t ? partial[t - 1] : 0;
#pragma unroll
    for (int k = 0; k < CH; k++) {
        int i = base + k;
        if (i < NN) {
            int st = prev + local[k];
            g_start[i] = st;
            g_fill[i]  = st;
        }
    }
    if (t == 1023) g_start[NN] = partial[1023];
}

// fill einfo + per-(j,r,dst) counts (h-independent, reused by both layers)
__global__ __launch_bounds__(256)
void k_fill(const int* __restrict__ src, const int* __restrict__ dst,
            const int* __restrict__ ea) {
    int e = blockIdx.x * 256 + threadIdx.x;
    if (e >= EE) return;
    int d = dst[e];
    int r0 = ea[(size_t)e * 3 + 0];
    int r1 = ea[(size_t)e * 3 + 1];
    int r2 = ea[(size_t)e * 3 + 2];
    int pos = atomicAdd(&g_fill[d], 1);
    g_einfo[pos] = (unsigned)src[e] | ((unsigned)r0 << 15)
                 | ((unsigned)r1 << 18) | ((unsigned)r2 << 21);
    atomicAdd(&g_cnt24[r0 * NN + d], 1);
    atomicAdd(&g_cnt24[(RR + r1) * NN + d], 1);
    atomicAdd(&g_cnt24[(2 * RR + r2) * NN + d], 1);
}

// ============================================================
// FUSED aggregation: one warp per dst; 24 fp32 buckets in smem;
// 4-deep explicit-register gather pipeline (edge ORDER preserved);
// counts precomputed in k_fill. fp16 mean-scaled output.
// ============================================================
__device__ __forceinline__ void bump(float* base, int jr, int lane, float4 v) {
    float4* b = (float4*)(base + (size_t)jr * HH + lane * 4);
    float4 t = *b;
    t.x += v.x; t.y += v.y; t.z += v.z; t.w += v.w;
    *b = t;
}
__device__ __forceinline__ void acc_edge(float* base, unsigned info, int lane, float4 v) {
    bump(base, (info >> 15) & 7, lane, v);
    bump(base, RR + ((info >> 18) & 7), lane, v);
    bump(base, 2 * RR + ((info >> 21) & 7), lane, v);
}

__global__ __launch_bounds__(64)
void k_agg(int layer) {
    __shared__ float buck[2][JR][HH];   // 24 KB

    int t = threadIdx.x, w = t >> 5, lane = t & 31;
    int d = blockIdx.x * 2 + w;
    const float* h = layer ? g_h1 : g_h0;
    float* mybuck = &buck[w][0][0];

    float4* bp = (float4*)mybuck;       // zero 24*128 floats = 768 float4
#pragma unroll
    for (int q = 0; q < JR; q++) bp[lane + q * 32] = make_float4(0.f, 0.f, 0.f, 0.f);
    __syncwarp();

    int s0 = g_start[d], s1 = g_start[d + 1];

    // 4-deep software pipeline, explicit registers (no indexed ring)
    unsigned i0 = 0, i1 = 0, i2 = 0, i3 = 0;
    float4 v0, v1, v2, v3;
    v0 = v1 = v2 = v3 = make_float4(0.f, 0.f, 0.f, 0.f);
    if (s0 + 0 < s1) { i0 = g_einfo[s0 + 0]; v0 = *(const float4*)(h + (size_t)(i0 & 0x7FFF) * HH + lane * 4); }
    if (s0 + 1 < s1) { i1 = g_einfo[s0 + 1]; v1 = *(const float4*)(h + (size_t)(i1 & 0x7FFF) * HH + lane * 4); }
    if (s0 + 2 < s1) { i2 = g_einfo[s0 + 2]; v2 = *(const float4*)(h + (size_t)(i2 & 0x7FFF) * HH + lane * 4); }
    if (s0 + 3 < s1) { i3 = g_einfo[s0 + 3]; v3 = *(const float4*)(h + (size_t)(i3 & 0x7FFF) * HH + lane * 4); }

    for (int idx = s0; idx < s1; idx += 4) {
        unsigned n0 = 0, n1 = 0, n2 = 0, n3 = 0;
        float4 w0, w1, w2, w3;
        w0 = w1 = w2 = w3 = make_float4(0.f, 0.f, 0.f, 0.f);
        if (idx + 4 < s1) { n0 = g_einfo[idx + 4]; w0 = *(const float4*)(h + (size_t)(n0 & 0x7FFF) * HH + lane * 4); }
        if (idx + 5 < s1) { n1 = g_einfo[idx + 5]; w1 = *(const float4*)(h + (size_t)(n1 & 0x7FFF) * HH + lane * 4); }
        if (idx + 6 < s1) { n2 = g_einfo[idx + 6]; w2 = *(const float4*)(h + (size_t)(n2 & 0x7FFF) * HH + lane * 4); }
        if (idx + 7 < s1) { n3 = g_einfo[idx + 7]; w3 = *(const float4*)(h + (size_t)(n3 & 0x7FFF) * HH + lane * 4); }

        acc_edge(mybuck, i0, lane, v0);
        if (idx + 1 < s1) acc_edge(mybuck, i1, lane, v1);
        if (idx + 2 < s1) acc_edge(mybuck, i2, lane, v2);
        if (idx + 3 < s1) acc_edge(mybuck, i3, lane, v3);

        i0 = n0; v0 = w0; i1 = n1; v1 = w1;
        i2 = n2; v2 = w2; i3 = n3; v3 = w3;
    }
    __syncwarp();

    // epilogue: scale by precomputed 1/cnt, convert to fp16, store
#pragma unroll
    for (int jr = 0; jr < JR; jr++) {
        int c = g_cnt24[jr * NN + d];
        float sc = 1.f / fmaxf((float)c, 1.f);
        float4 bv = *(float4*)(mybuck + (size_t)jr * HH + lane * 4);
        bv.x *= sc; bv.y *= sc; bv.z *= sc; bv.w *= sc;
        __half2 ha = __floats2half2_rn(bv.x, bv.y);
        __half2 hb = __floats2half2_rn(bv.z, bv.w);
        unsigned ua = *(unsigned*)&ha;
        unsigned ub = *(unsigned*)&hb;
        *(uint2*)(g_sums_h + ((size_t)jr * NN + d) * 64 + lane * 2) = make_uint2(ua, ub);
    }
}

// ============================================================
// transform (ALL 3 j in one launch, blockIdx.y = j):
// agg[j][n, b*32+d] = sum_r sum_c meanS[j][r][n][c] * W[layer,j][r,b,c,d]
// inner loop: LDS.128 (ulonglong2) -> 2x fma.rn.f32x2
// ============================================================
__global__ __launch_bounds__(256)
void k_transform(const float* __restrict__ Wl) {
    __shared__ float S[32][HH];     // 16 KB

    int j = blockIdx.y;
    const float* W = Wl + (size_t)j * RR * BB * CC * CC;
    const __half2* Sb = g_sums_h + (size_t)j * RR * NN * 64;
    int t = threadIdx.x;
    int nodeBase = blockIdx.x * 32;
    int o = t & 127;
    int grp = t >> 7;               // 0 / 1 (16 nodes each)
    int b = o >> 5, d = o & 31;

    unsigned long long acc2[16];
#pragma unroll
    for (int q = 0; q < 16; q++) acc2[q] = 0ull;

    for (int r = 0; r < RR; r++) {
        __syncthreads();
        // stage: fp16 -> fp32 smem (32 nodes x 64 half2 per block per r)
#pragma unroll
        for (int q = 0; q < 8; q++) {
            int lin = t + q * 256;              // 0..2047
            int nl = lin >> 6, c2 = lin & 63;
            __half2 hv = Sb[((size_t)r * NN + nodeBase + nl) * 64 + c2];
            float2 f = __half22float2(hv);
            *(float2*)&S[nl][2 * c2] = f;
        }
        __syncthreads();

        unsigned long long wp[16];
#pragma unroll
        for (int c2 = 0; c2 < 16; c2++) {
            const float* wq = W + ((size_t)((r * BB + b) * CC + 2 * c2)) * CC + d;
            wp[c2] = pk2(__ldg(wq), __ldg(wq + CC));
        }

#pragma unroll
        for (int q = 0; q < 16; q++) {
            int nl = grp * 16 + q;
            const ulonglong2* Srow = (const ulonglong2*)&S[nl][b * CC];  // 16B aligned
#pragma unroll
            for (int c4 = 0; c4 < 8; c4++) {
                ulonglong2 p = Srow[c4];        // LDS.128 -> two b64 halves
                FMA2(acc2[q], p.x, wp[2 * c4 + 0]);
                FMA2(acc2[q], p.y, wp[2 * c4 + 1]);
            }
        }
    }

    float* aggj = g_agg + (size_t)j * NN * HH;
#pragma unroll
    for (int q = 0; q < 16; q++) {
        int nl = grp * 16 + q;
        float lo, hi;
        upk2(acc2[q], lo, hi);
        aggj[((size_t)(nodeBase + nl)) * HH + o] = lo + hi;
    }
}

// ============================================================
// root (ALL 3 j in one launch, blockIdx.y = j):
// out[j][row,:] = relu( (row<N ? agg[j] : 0) + h[row,:] @ root[j] + bias[j] )
// g_h1 resolved in DEVICE code (extOut==nullptr selector).
// ============================================================
__global__ __launch_bounds__(512)
void root_fused_kernel(const float* __restrict__ rootL, const float* __restrict__ biasL,
                       int Np, float* __restrict__ extOut, int layer) {
    __shared__ float hT[32][64];    // [k][row]
    __shared__ float rS[32][128];   // [k][col]

    int j = blockIdx.y;
    const float* root = rootL + (size_t)j * HH * HH;
    const float* bias = biasL + (size_t)j * HH;
    const float* hin = layer ? g_h1 : g_h0;
    float* outp = (extOut ? extOut : g_h1) + (size_t)j * (size_t)Np * HH;
    const float* aggj = g_agg + (size_t)j * NN * HH;

    int tx = threadIdx.x;
    int row0 = blockIdx.x * 64;
    int r4 = (tx & 15) * 4;
    int c4 = (tx >> 4) * 4;

    unsigned long long acc2[4][2];
#pragma unroll
    for (int i = 0; i < 4; i++) { acc2[i][0] = 0ull; acc2[i][1] = 0ull; }

    for (int k0 = 0; k0 < HH; k0 += 32) {
        __syncthreads();
        {   // hT: 64 rows x 32 k (transposed store), one float4 per thread
            int row = tx >> 3;
            int kq = (tx & 7) * 4;
            float4 hv = make_float4(0.f, 0.f, 0.f, 0.f);
            int grow = row0 + row;
            if (grow < Np)
                hv = *(const float4*)(hin + (size_t)grow * HH + k0 + kq);
            hT[kq + 0][row] = hv.x;
            hT[kq + 1][row] = hv.y;
            hT[kq + 2][row] = hv.z;
            hT[kq + 3][row] = hv.w;
        }
#pragma unroll
        for (int q = 0; q < 2; q++) {   // rS: 32 k x 128 cols
            int lin = tx + q * 512;
            int k = lin >> 5;
            int cq = (lin & 31) * 4;
            *(float4*)&rS[k][cq] = *(const float4*)(root + (size_t)(k0 + k) * HH + cq);
        }
        __syncthreads();

#pragma unroll
        for (int k = 0; k < 32; k++) {
            float4 a = *(const float4*)&hT[k][r4];
            ulonglong2 bp = *(const ulonglong2*)&rS[k][c4];   // LDS.128, 16B aligned
            float av[4] = {a.x, a.y, a.z, a.w};
#pragma unroll
            for (int i = 0; i < 4; i++) {
                unsigned long long ai = pk2(av[i], av[i]);
                FMA2(acc2[i][0], ai, bp.x);
                FMA2(acc2[i][1], ai, bp.y);
            }
        }
    }

    float bv0 = bias[c4 + 0], bv1 = bias[c4 + 1], bv2 = bias[c4 + 2], bv3 = bias[c4 + 3];
#pragma unroll
    for (int i = 0; i < 4; i++) {
        int row = row0 + r4 + i;
        if (row >= Np) break;
        float4 o4;
        upk2(acc2[i][0], o4.x, o4.y);
        upk2(acc2[i][1], o4.z, o4.w);
        o4.x += bv0; o4.y += bv1; o4.z += bv2; o4.w += bv3;
        if (row < NN) {
            const float4 ag = *(const float4*)(aggj + (size_t)row * HH + c4);
            o4.x += ag.x; o4.y += ag.y; o4.z += ag.z; o4.w += ag.w;
        }
        o4.x = fmaxf(o4.x, 0.f);
        o4.y = fmaxf(o4.y, 0.f);
        o4.z = fmaxf(o4.z, 0.f);
        o4.w = fmaxf(o4.w, 0.f);
        *(float4*)(outp + (size_t)row * HH + c4) = o4;
    }
}

// ============================================================
extern "C" void kernel_launch(void* const* d_in, const int* in_sizes, int n_in,
                              void* d_out, int out_size) {
    const float* x  = (const float*)d_in[0];
    const int*   ei = (const int*)  d_in[1];
    const int*   ea = (const int*)  d_in[2];
    const float* fe = (const float*)d_in[3];
    const float* cw = (const float*)d_in[4];
    const float* cr = (const float*)d_in[5];
    const float* cb = (const float*)d_in[6];
    float* out = (float*)d_out;

    const int* src = ei;
    const int* dst = ei + EE;

    gemm_in_kernel<<<NN / 2, 256>>>(x, fe);     // also zeroes g_deg
    k_count<<<(EE + 255) / 256, 256>>>(dst);    // also zeroes g_cnt24
    k_prefix<<<1, 1024>>>();
    k_fill<<<(EE + 255) / 256, 256>>>(src, dst, ea);

    for (int layer = 0; layer < 2; layer++) {
        int Np = (layer == 0) ? NN : 3 * NN;

        k_agg<<<NN / 2, 64>>>(layer);           // fused gather+bucket for all 3 j

        const float* Wl    = cw + (size_t)layer * 3 * RR * BB * CC * CC;
        const float* rootL = cr + (size_t)layer * 3 * HH * HH;
        const float* biasL = cb + (size_t)layer * 3 * HH;

        dim3 gT(NN / 32, 3);
        k_transform<<<gT, 256>>>(Wl);           // all 3 j in one launch

        // layer 0 -> device-resolved g_h1 (extOut = nullptr); layer 1 -> d_out
        float* extOut = (layer == 0) ? nullptr : out;
        dim3 gR((Np + 63) / 64, 3);
        root_fused_kernel<<<gR, 512>>>(rootL, biasL, Np, extOut, layer);
    }
}